// round 15
// baseline (speedup 1.0000x reference)
#include <cuda_runtime.h>
#include <cuda_bf16.h>
#include <mma.h>
#include <cstdint>

using namespace nvcuda;

#define Nn 40000
#define Ee 640000
#define ET 680000   /* Ee + Nn self loops */
#define HIDc 128
#define H1c 4
#define D1 512      /* H1*HID */
#define IND 5
#define EDD 11
#define NEG 0.2f

#define EAP_BLOCKS 160
#define EAP_ROWS 4000

#define MROWS 40064          /* 313 * 128, padded M */
#define SC_BLOCKS 157        /* ceil(40000/256) scan blocks */
#define N1_BLOCKS 1250       /* node1 blocks */

/* k_init block ranges */
#define IB_EAP  160
#define IB_W2   64           /* 65536 / (256*4) */
#define IB_CNT  665          /* ceil(680000/(256*4)) */
#define IB_US2  128          /* 1024 warp-outputs: us2/ud2 */
#define IB_MISC 12           /* 95 warp-outputs: aev1,aev2,us1,ud1 */
#define IB_TOTAL (IB_EAP + IB_W2 + IB_CNT + IB_US2 + IB_MISC)

// ---------------- scratch (device globals; no allocation allowed) ----------
__device__ __nv_bfloat16 g_h1b[(size_t)MROWS * D1];     // padded rows stay zero
__device__ uint32_t g_xh2b[(size_t)MROWS * 64];         // bf16x2 packed
__device__ __nv_bfloat16 g_W2b[D1 * HIDc];
__device__ float g_x8[(size_t)Nn * 8];                  // padded x rows (32B)
__device__ float g_as1[Nn * H1c];
__device__ float g_ad1[Nn * H1c];
__device__ float g_as2[Nn];
__device__ float g_ad2[Nn];
__device__ int   g_deg[Nn];
__device__ int   g_rowstart[Nn + 1];
__device__ int   g_cursor[Nn];
__device__ int   g_flag[SC_BLOCKS];
__device__ int   g_aggv[SC_BLOCKS];
__device__ int   g_inclv[SC_BLOCKS];
__device__ float4 g_csrA[ET];   // {ex0,ex1,ex2,ex3}
__device__ float4 g_csrB[ET];   // {x0,x1,x2,x3}
__device__ float4 g_csrC[ET];   // {x4, e2, src, -}
__device__ float g_eamean[EDD];
__device__ float g_eapart[EAP_BLOCKS * EDD];
__device__ float g_aev1[H1c * EDD];
__device__ float g_aev2[EDD];
__device__ float g_us1[H1c * IND];
__device__ float g_ud1[H1c * IND];
__device__ float g_us2[D1];
__device__ float g_ud2[D1];

// ---------------- small helpers --------------------------------------------
__device__ __forceinline__ uint32_t smem_u32(const void* p) {
    uint32_t a;
    asm("{ .reg .u64 t; cvta.to.shared.u64 t, %1; cvt.u32.u64 %0, t; }" : "=r"(a) : "l"(p));
    return a;
}
__device__ __forceinline__ void cp_async16(uint32_t dst, const void* src) {
    asm volatile("cp.async.cg.shared.global [%0], [%1], 16;" :: "r"(dst), "l"(src));
}
#define CP_COMMIT() asm volatile("cp.async.commit_group;" ::: "memory")
#define CP_WAIT1()  asm volatile("cp.async.wait_group 1;" ::: "memory")
#define CP_WAIT0()  asm volatile("cp.async.wait_group 0;" ::: "memory")

__device__ __forceinline__ float warp_red(float v) {
#pragma unroll
    for (int off = 16; off > 0; off >>= 1)
        v += __shfl_down_sync(0xffffffffu, v, off);
    return v;
}

__device__ __forceinline__ float warp_dot128(const float* a, const float* b, int lane) {
    float s = 0.f;
#pragma unroll
    for (int c = 0; c < 4; c++) s = fmaf(a[lane + 32 * c], b[lane + 32 * c], s);
    return warp_red(s);
}

// block-wide inclusive scan helper (256 threads)
__device__ __forceinline__ int block_scan_incl(int v, int t, int* total_out) {
    int lane = t & 31, w = t >> 5;
    int sv = v;
#pragma unroll
    for (int off = 1; off < 32; off <<= 1) {
        int nv = __shfl_up_sync(0xffffffffu, sv, off);
        if (lane >= off) sv += nv;
    }
    __shared__ int ws[8];
    __shared__ int wo[8];
    __shared__ int tot;
    if (lane == 31) ws[w] = sv;
    __syncthreads();
    if (t == 0) {
        int run = 0;
#pragma unroll
        for (int k = 0; k < 8; k++) { wo[k] = run; run += ws[k]; }
        tot = run;
    }
    __syncthreads();
    *total_out = tot;
    return sv + wo[w];
}

// ---------------- kernels --------------------------------------------------

// fused: ea partial sums | W2->bf16 | degree count | u/aev precompute
__global__ void k_init(const float* __restrict__ ea,  const float* __restrict__ W2,
                       const int*   __restrict__ ei,
                       const float* __restrict__ W1,  const float* __restrict__ We1,
                       const float* __restrict__ We2,
                       const float* __restrict__ as1, const float* __restrict__ ad1,
                       const float* __restrict__ ae1,
                       const float* __restrict__ as2, const float* __restrict__ ad2,
                       const float* __restrict__ ae2) {
    int b = blockIdx.x, t = threadIdx.x;
    if (b < IB_EAP) {
        __shared__ float sm[256 * EDD];
        float loc[EDD];
#pragma unroll
        for (int d = 0; d < EDD; d++) loc[d] = 0.f;
        int r0 = b * EAP_ROWS;
        for (int r = t; r < EAP_ROWS; r += 256) {
            const float* p = ea + (size_t)(r0 + r) * EDD;
#pragma unroll
            for (int d = 0; d < EDD; d++) loc[d] += p[d];
        }
#pragma unroll
        for (int d = 0; d < EDD; d++) sm[t * EDD + d] = loc[d];
        __syncthreads();
        for (int off = 128; off > 0; off >>= 1) {
            if (t < off) {
#pragma unroll
                for (int d = 0; d < EDD; d++) sm[t * EDD + d] += sm[(t + off) * EDD + d];
            }
            __syncthreads();
        }
        if (t < EDD) g_eapart[b * EDD + t] = sm[t];
    } else if (b < IB_EAP + IB_W2) {
        int idx = ((b - IB_EAP) * 256 + t) * 4;
        float4 v = *(const float4*)&W2[idx];
        __nv_bfloat162 lo = __float22bfloat162_rn(make_float2(v.x, v.y));
        __nv_bfloat162 hi = __float22bfloat162_rn(make_float2(v.z, v.w));
        *(uint2*)&g_W2b[idx] = make_uint2(*(uint32_t*)&lo, *(uint32_t*)&hi);
    } else if (b < IB_EAP + IB_W2 + IB_CNT) {
        int e0 = ((b - IB_EAP - IB_W2) * 256 + t) * 4;
#pragma unroll
        for (int k = 0; k < 4; k++) {
            int e = e0 + k;
            if (e < ET) {
                int d = (e < Ee) ? ei[Ee + e] : (e - Ee);
                atomicAdd(&g_deg[d], 1);
            }
        }
    } else if (b < IB_EAP + IB_W2 + IB_CNT + IB_US2) {
        int g = (b - IB_EAP - IB_W2 - IB_CNT) * 8 + (t >> 5);   // 0..1023
        int lane = t & 31;
        if (g < 512) {
            float s = warp_dot128(W2 + (size_t)g * HIDc, as2, lane);
            if (lane == 0) g_us2[g] = s;
        } else {
            int k = g - 512;
            float s = warp_dot128(W2 + (size_t)k * HIDc, ad2, lane);
            if (lane == 0) g_ud2[k] = s;
        }
    } else {
        int g = (b - IB_EAP - IB_W2 - IB_CNT - IB_US2) * 8 + (t >> 5);  // 0..95
        int lane = t & 31;
        if (g < 44) {                       // aev1[h][d]
            int h = g / EDD, d = g % EDD;
            float s = 0.f;
#pragma unroll
            for (int c = 0; c < 4; c++)
                s = fmaf(We1[d * D1 + h * HIDc + lane + 32 * c],
                         ae1[h * HIDc + lane + 32 * c], s);
            s = warp_red(s);
            if (lane == 0) g_aev1[g] = s;
        } else if (g < 55) {                // aev2[d]
            int d = g - 44;
            float s = warp_dot128(We2 + (size_t)d * HIDc, ae2, lane);
            if (lane == 0) g_aev2[d] = s;
        } else if (g < 75) {                // us1[h*5+d]
            int o = g - 55, h = o / IND, d = o % IND;
            float s = 0.f;
#pragma unroll
            for (int c = 0; c < 4; c++)
                s = fmaf(W1[d * D1 + h * HIDc + lane + 32 * c],
                         as1[h * HIDc + lane + 32 * c], s);
            s = warp_red(s);
            if (lane == 0) g_us1[o] = s;
        } else if (g < 95) {                // ud1[h*5+d]
            int o = g - 75, h = o / IND, d = o % IND;
            float s = 0.f;
#pragma unroll
            for (int c = 0; c < 4; c++)
                s = fmaf(W1[d * D1 + h * HIDc + lane + 32 * c],
                         ad1[h * HIDc + lane + 32 * c], s);
            s = warp_red(s);
            if (lane == 0) g_ud1[o] = s;
        }
    }
}

// fused: decoupled-lookback scan (blocks 0..156) | eamean (157) | node1 (158+)
__global__ void k_mid(const float* __restrict__ x) {
    int b = blockIdx.x, t = threadIdx.x;
    if (b < SC_BLOCKS) {
        int i = b * 256 + t;
        int v = (i < Nn) ? g_deg[i] : 0;
        int tot;
        int incl = block_scan_incl(v, t, &tot);
        __shared__ int s_off;
        volatile int* flag = g_flag;
        volatile int* aggv = g_aggv;
        volatile int* inclv = g_inclv;
        if (t == 0) {
            if (b == 0) {
                inclv[0] = tot; __threadfence(); flag[0] = 2;
                s_off = 0;
            } else {
                aggv[b] = tot; __threadfence(); flag[b] = 1;
                int run = 0, j = b - 1;
                while (true) {
                    int f;
                    do { f = flag[j]; } while (f == 0);
                    if (f == 2) { run += inclv[j]; break; }
                    run += aggv[j]; j--;
                }
                inclv[b] = run + tot; __threadfence(); flag[b] = 2;
                s_off = run;
            }
        }
        __syncthreads();
        int r = s_off + incl - v;
        if (i < Nn) { g_rowstart[i] = r; g_cursor[i] = r; }
        if (b == SC_BLOCKS - 1 && t == 255) g_rowstart[Nn] = ET;
    } else if (b == SC_BLOCKS) {
        int w = t >> 5, lane = t & 31;
        for (int col = w; col < EDD; col += 8) {
            float s = 0.f;
            for (int p = lane; p < EAP_BLOCKS; p += 32) s += g_eapart[p * EDD + col];
            s = warp_red(s);
            if (lane == 0) g_eamean[col] = s / (float)Ee;
        }
    } else {
        int idx = (b - SC_BLOCKS - 1) * 256 + t;
        int n = idx >> 3;
        if (n >= Nn) return;
        int r = idx & 7;
        int h = r & 3;
        const float* xp = x + (size_t)n * IND;
        g_x8[(size_t)n * 8 + r] = (r < IND) ? xp[r] : 0.f;
        const float* u = (r < 4) ? (g_us1 + h * IND) : (g_ud1 + h * IND);
        float s = 0.f;
#pragma unroll
        for (int d = 0; d < IND; d++) s += xp[d] * u[d];
        if (r < 4) g_as1[n * H1c + h] = s;
        else       g_ad1[n * H1c + h] = s;
    }
}

// CSR scatter, SoA: A={ex0..3} B={x0..3} C={x4,e2,src}.
// exp(leakyrelu(alpha1)) computed here (MUFU-idle kernel); x carried inline so
// k_agg1's gather is fully streaming.
__global__ void k_scatter(const int* __restrict__ ei, const float* __restrict__ ea) {
    int e = blockIdx.x * blockDim.x + threadIdx.x;
    if (e >= ET) return;
    int s, d;
    float v[EDD];
    if (e < Ee) {
        s = ei[e]; d = ei[Ee + e];
        const float* p = ea + (size_t)e * EDD;
#pragma unroll
        for (int k = 0; k < EDD; k++) v[k] = p[k];
    } else {
        s = e - Ee; d = s;
#pragma unroll
        for (int k = 0; k < EDD; k++) v[k] = g_eamean[k];
    }
    int pos = atomicAdd(&g_cursor[d], 1);
    float e2 = 0.f;
#pragma unroll
    for (int k = 0; k < EDD; k++) e2 += v[k] * g_aev2[k];

    float4 asv = *(const float4*)&g_as1[s * H1c];
    float4 adv = *(const float4*)&g_ad1[d * H1c];
    float al[H1c];
#pragma unroll
    for (int h = 0; h < H1c; h++) {
        float ed = 0.f;
#pragma unroll
        for (int k = 0; k < EDD; k++) ed += v[k] * g_aev1[h * EDD + k];
        float a = ((h == 0) ? asv.x : (h == 1) ? asv.y : (h == 2) ? asv.z : asv.w)
                + ((h == 0) ? adv.x : (h == 1) ? adv.y : (h == 2) ? adv.z : adv.w) + ed;
        a = (a > 0.f) ? a : NEG * a;
        al[h] = __expf(a);
    }
    const float* xp = g_x8 + (size_t)s * 8;
    float4 xv4 = __ldg((const float4*)xp);
    float xv5 = __ldg(xp + 4);
    g_csrA[pos] = make_float4(al[0], al[1], al[2], al[3]);
    g_csrB[pos] = xv4;
    g_csrC[pos] = make_float4(xv5, e2, __int_as_float(s), 0.f);
}

// layer-1 softmax + aggregation + projection; gather is pure streaming SoA.
__global__ __launch_bounds__(256) void k_agg1(const float* __restrict__ W1,
                                              const float* __restrict__ b1) {
    __shared__ float s_ax[8][21];
    __shared__ uint32_t s_h1[8][256];       // bf16x2 packed, 8 KB
    __shared__ float s_u[D1];
    __shared__ float s_ud[D1];
    int t = threadIdx.x;
    int w = t >> 5, lane = t & 31;
    int n0 = blockIdx.x * 8;
    int n = n0 + w;                         // Nn % 8 == 0

#pragma unroll
    for (int i = 0; i < 2; i++) {
        s_u [t + i * 256] = g_us2[t + i * 256];
        s_ud[t + i * 256] = g_ud2[t + i * 256];
    }

    int base = g_rowstart[n];
    int deg  = g_rowstart[n + 1] - base;

    float den[H1c];
    float ax[H1c][IND];
#pragma unroll
    for (int h = 0; h < H1c; h++) {
        den[h] = 0.f;
#pragma unroll
        for (int d = 0; d < IND; d++) ax[h][d] = 0.f;
    }

    for (int i = lane; i < deg; i += 32) {
        float4 exv = g_csrA[base + i];
        float4 xa  = g_csrB[base + i];
        float4 xc  = g_csrC[base + i];
        float e0 = exv.x, e1 = exv.y, e2 = exv.z, e3 = exv.w;
        den[0] += e0; den[1] += e1; den[2] += e2; den[3] += e3;
        float xv[IND] = {xa.x, xa.y, xa.z, xa.w, xc.x};
#pragma unroll
        for (int d = 0; d < IND; d++) {
            ax[0][d] = fmaf(e0, xv[d], ax[0][d]);
            ax[1][d] = fmaf(e1, xv[d], ax[1][d]);
            ax[2][d] = fmaf(e2, xv[d], ax[2][d]);
            ax[3][d] = fmaf(e3, xv[d], ax[3][d]);
        }
    }
#pragma unroll
    for (int off = 16; off > 0; off >>= 1) {
#pragma unroll
        for (int h = 0; h < H1c; h++) {
            den[h] += __shfl_xor_sync(0xffffffffu, den[h], off);
#pragma unroll
            for (int d = 0; d < IND; d++)
                ax[h][d] += __shfl_xor_sync(0xffffffffu, ax[h][d], off);
        }
    }
    if (lane < 20) {
        int h = lane / IND, d = lane % IND;
        s_ax[w][lane] = ax[h][d] * (1.f / (den[h] + 1e-16f));
    }
    __syncthreads();

    int c0 = t * 2;
    int h2 = c0 >> 7;
    float2 wv[IND];
#pragma unroll
    for (int d = 0; d < IND; d++) wv[d] = *(const float2*)&W1[d * D1 + c0];
    float2 bb = *(const float2*)&b1[c0];

#pragma unroll
    for (int q = 0; q < 8; q++) {
        float a0 = bb.x, a1 = bb.y;
#pragma unroll
        for (int d = 0; d < IND; d++) {
            float av = s_ax[q][h2 * IND + d];
            a0 = fmaf(av, wv[d].x, a0);
            a1 = fmaf(av, wv[d].y, a1);
        }
        a0 = (a0 > 0.f) ? a0 : 0.f;
        a1 = (a1 > 0.f) ? a1 : 0.f;
        __nv_bfloat162 bv = __float22bfloat162_rn(make_float2(a0, a1));
        *(__nv_bfloat162*)(g_h1b + (size_t)(n0 + q) * D1 + c0) = bv;
        s_h1[q][t] = *(uint32_t*)&bv;
    }
    __syncthreads();

    float s2 = 0.f, d2v = 0.f;
#pragma unroll
    for (int j = 0; j < 8; j++) {
        int c = j * 32 + lane;
        uint32_t raw = s_h1[w][c];
        float2 f = __bfloat1622float2(*(__nv_bfloat162*)&raw);
        s2  = fmaf(f.x, s_u [2 * c], fmaf(f.y, s_u [2 * c + 1], s2));
        d2v = fmaf(f.x, s_ud[2 * c], fmaf(f.y, s_ud[2 * c + 1], d2v));
    }
    s2  = warp_red(s2);
    d2v = warp_red(d2v);
    if (lane == 0) { g_as2[n] = s2; g_ad2[n] = d2v; }
}

// xh2 = h1 @ W2 : bf16 wmma (HMMA), 128x128 CTA tile, K chunks of 64,
// cp.async double-buffered; bf16x2 packed output staged through smem.
#define KC 64
#define A_ELEMS 9216    /* 128 * 72 */
#define B_ELEMS 8704    /* 64 * 136 */
#define A_BYTES 18432
#define B_BYTES 17408
#define GSM_TOTAL (2 * (A_BYTES + B_BYTES))   /* 71680 >= 65536 for C staging */

__global__ __launch_bounds__(256, 2) void k_gemm() {
    extern __shared__ char smc[];
    __nv_bfloat16* As = (__nv_bfloat16*)smc;                     // [2][128][72]
    __nv_bfloat16* Bs = (__nv_bfloat16*)(smc + 2 * A_BYTES);     // [2][64][136]
    uint32_t smA = smem_u32(As);
    uint32_t smB = smem_u32(Bs);

    int t = threadIdx.x;
    int wid = t >> 5;
    int row0 = blockIdx.x * 128;
    int wm0 = (wid >> 2) * 64;     // 0 or 64
    int wn0 = (wid & 3) * 32;      // 0,32,64,96

    wmma::fragment<wmma::accumulator, 16, 16, 16, float> acc[4][2];
#pragma unroll
    for (int m = 0; m < 4; m++)
#pragma unroll
        for (int n = 0; n < 2; n++) wmma::fill_fragment(acc[m][n], 0.f);

    auto load_chunk = [&](int buf, int k0) {
#pragma unroll
        for (int i = 0; i < 4; i++) {
            int v = i * 256 + t;
            int r = v >> 3, c8 = v & 7;                 // A: 128 rows x 8 uint4
            cp_async16(smA + (uint32_t)(buf * A_ELEMS + r * 72 + c8 * 8) * 2,
                       g_h1b + (size_t)(row0 + r) * D1 + k0 + c8 * 8);
        }
#pragma unroll
        for (int i = 0; i < 4; i++) {
            int v = i * 256 + t;
            int r = v >> 4, c8 = v & 15;                // B: 64 rows x 16 uint4
            cp_async16(smB + (uint32_t)(buf * B_ELEMS + r * 136 + c8 * 8) * 2,
                       g_W2b + (size_t)(k0 + r) * HIDc + c8 * 8);
        }
        CP_COMMIT();
    };

    load_chunk(0, 0);
    int buf = 0;
#pragma unroll
    for (int c = 0; c < 8; c++) {
        if (c < 7) load_chunk(buf ^ 1, (c + 1) * KC);
        if (c < 7) CP_WAIT1(); else CP_WAIT0();
        __syncthreads();

        const __nv_bfloat16* Ab = As + buf * A_ELEMS;
        const __nv_bfloat16* Bb = Bs + buf * B_ELEMS;
#pragma unroll
        for (int kk = 0; kk < 4; kk++) {
            wmma::fragment<wmma::matrix_a, 16, 16, 16, __nv_bfloat16, wmma::row_major> af[4];
            wmma::fragment<wmma::matrix_b, 16, 16, 16, __nv_bfloat16, wmma::row_major> bf[2];
#pragma unroll
            for (int m = 0; m < 4; m++)
                wmma::load_matrix_sync(af[m], Ab + (wm0 + m * 16) * 72 + kk * 16, 72);
#pragma unroll
            for (int n = 0; n < 2; n++)
                wmma::load_matrix_sync(bf[n], Bb + (kk * 16) * 136 + wn0 + n * 16, 136);
#pragma unroll
            for (int m = 0; m < 4; m++)
#pragma unroll
                for (int n = 0; n < 2; n++)
                    wmma::mma_sync(acc[m][n], af[m], bf[n], acc[m][n]);
        }
        __syncthreads();
        buf ^= 1;
    }

    // stage fp32 C in smem, emit packed bf16x2
    float* Cs = (float*)smc;    // 128*128 fp32 = 64KB
#pragma unroll
    for (int m = 0; m < 4; m++)
#pragma unroll
        for (int n = 0; n < 2; n++)
            wmma::store_matrix_sync(Cs + (size_t)(wm0 + m * 16) * 128 + wn0 + n * 16,
                                    acc[m][n], 128, wmma::mem_row_major);
    __syncthreads();
#pragma unroll
    for (int j = 0; j < 32; j++) {
        int idx = j * 256 + t;          // 8192 bf16x2 pairs
        int row = idx >> 6, cp = idx & 63;
        float2 f = *(const float2*)&Cs[row * 128 + cp * 2];
        __nv_bfloat162 bv = __float22bfloat162_rn(f);
        g_xh2b[(size_t)(row0 + row) * 64 + cp] = *(uint32_t*)&bv;
    }
}

// layer-2 softmax + aggregation + final linear + sigmoid, warp-per-node.
__global__ __launch_bounds__(256) void k_agg2(const float* __restrict__ b2,
                                              const float* __restrict__ Wfc,
                                              const float* __restrict__ bfc,
                                              float* __restrict__ out) {
    int t = threadIdx.x;
    int w = t >> 5, lane = t & 31;
    int n = blockIdx.x * 8 + w;            // Nn % 8 == 0
    int base = g_rowstart[n];
    int deg  = g_rowstart[n + 1] - base;
    float ad = g_ad2[n];

    float acc0 = 0.f, acc1 = 0.f, acc2 = 0.f, acc3 = 0.f;
    float den = 0.f;

    for (int b0 = 0; b0 < deg; b0 += 32) {
        float ex = 0.f; int src = 0;
        int i = b0 + lane;
        if (i < deg) {
            float4 f = g_csrC[base + i];
            src = __float_as_int(f.z);
            float al = g_as2[src] + ad + f.y;
            al = (al > 0.f) ? al : NEG * al;
            ex = __expf(al);
        }
        den += ex;
        int cnt = deg - b0; if (cnt > 32) cnt = 32;
        for (int j = 0; j < cnt; j++) {
            float exj = __shfl_sync(0xffffffffu, ex, j);
            int srcj  = __shfl_sync(0xffffffffu, src, j);
            uint2 raw = *(const uint2*)&g_xh2b[(size_t)srcj * 64 + lane * 2];
            float2 f0 = __bfloat1622float2(*(__nv_bfloat162*)&raw.x);
            float2 f1 = __bfloat1622float2(*(__nv_bfloat162*)&raw.y);
            acc0 = fmaf(exj, f0.x, acc0);
            acc1 = fmaf(exj, f0.y, acc1);
            acc2 = fmaf(exj, f1.x, acc2);
            acc3 = fmaf(exj, f1.y, acc3);
        }
    }
#pragma unroll
    for (int off = 16; off > 0; off >>= 1)
        den += __shfl_xor_sync(0xffffffffu, den, off);
    float inv = 1.f / (den + 1e-16f);

    float4 bb = *(const float4*)&b2[lane * 4];
    float4 wf = *(const float4*)&Wfc[lane * 4];
    float h0 = acc0 * inv + bb.x; h0 = (h0 > 0.f) ? h0 : 0.f;
    float h1 = acc1 * inv + bb.y; h1 = (h1 > 0.f) ? h1 : 0.f;
    float h2 = acc2 * inv + bb.z; h2 = (h2 > 0.f) ? h2 : 0.f;
    float h3 = acc3 * inv + bb.w; h3 = (h3 > 0.f) ? h3 : 0.f;
    float part = fmaf(h0, wf.x, fmaf(h1, wf.y, fmaf(h2, wf.z, h3 * wf.w)));
    part = warp_red(part);
    if (lane == 0) {
        float z = part + bfc[0];
        out[n] = 1.f / (1.f + __expf(-z));
    }
}

// ---------------- launcher -------------------------------------------------

extern "C" void kernel_launch(void* const* d_in, const int* in_sizes, int n_in,
                              void* d_out, int out_size) {
    const float* x    = (const float*)d_in[0];
    const int*   ei   = (const int*)  d_in[1];
    const float* ea   = (const float*)d_in[2];
    const float* W1   = (const float*)d_in[3];
    const float* We1  = (const float*)d_in[4];
    const float* as1v = (const float*)d_in[5];
    const float* ad1v = (const float*)d_in[6];
    const float* ae1v = (const float*)d_in[7];
    const float* b1   = (const float*)d_in[8];
    const float* W2   = (const float*)d_in[9];
    const float* We2  = (const float*)d_in[10];
    const float* as2v = (const float*)d_in[11];
    const float* ad2v = (const float*)d_in[12];
    const float* ae2v = (const float*)d_in[13];
    const float* b2   = (const float*)d_in[14];
    const float* Wfc  = (const float*)d_in[15];
    const float* bfc  = (const float*)d_in[16];
    float* out = (float*)d_out;

    static void* p_deg = nullptr;
    static void* p_flag = nullptr;
    if (!p_deg) {
        cudaFuncSetAttribute(k_gemm, cudaFuncAttributeMaxDynamicSharedMemorySize, GSM_TOTAL);
        cudaGetSymbolAddress(&p_deg, g_deg);
        cudaGetSymbolAddress(&p_flag, g_flag);
    }

    cudaMemsetAsync(p_deg, 0, Nn * sizeof(int));
    cudaMemsetAsync(p_flag, 0, SC_BLOCKS * sizeof(int));
    k_init<<<IB_TOTAL, 256>>>(ea, W2, ei, W1, We1, We2,
                              as1v, ad1v, ae1v, as2v, ad2v, ae2v);
    k_mid<<<SC_BLOCKS + 1 + N1_BLOCKS, 256>>>(x);
    k_scatter<<<(ET + 255) / 256, 256>>>(ei, ea);
    k_agg1<<<Nn / 8, 256>>>(W1, b1);
    k_gemm<<<MROWS / 128, 256, GSM_TOTAL>>>();
    k_agg2<<<Nn / 8, 256>>>(b2, Wfc, bfc, out);
}

// round 16
// speedup vs baseline: 1.0871x; 1.0871x over previous
#include <cuda_runtime.h>
#include <cuda_bf16.h>
#include <mma.h>
#include <cstdint>

using namespace nvcuda;

#define Nn 40000
#define Ee 640000
#define ET 680000   /* Ee + Nn self loops */
#define HIDc 128
#define H1c 4
#define D1 512      /* H1*HID */
#define IND 5
#define EDD 11
#define NEG 0.2f

#define EAP_BLOCKS 160
#define EAP_ROWS 4000

#define MROWS 40064          /* 313 * 128, padded M */
#define SC_BLOCKS 157        /* ceil(40000/256) scan blocks */
#define N1_BLOCKS 1250       /* node1 blocks */

/* k_init block ranges */
#define IB_EAP  160
#define IB_W2   64           /* 65536 / (256*4) */
#define IB_CNT  665          /* ceil(680000/(256*4)) */
#define IB_US2  128          /* 1024 warp-outputs: us2/ud2 */
#define IB_MISC 12           /* 95 warp-outputs: aev1,aev2,us1,ud1 */
#define IB_TOTAL (IB_EAP + IB_W2 + IB_CNT + IB_US2 + IB_MISC)

// ---------------- scratch (device globals; no allocation allowed) ----------
__device__ __nv_bfloat16 g_h1b[(size_t)MROWS * D1];     // padded rows stay zero
__device__ uint32_t g_xh2b[(size_t)MROWS * 64];         // bf16x2 packed
__device__ __nv_bfloat16 g_W2b[D1 * HIDc];
__device__ float g_x8[(size_t)Nn * 8];                  // padded x rows (32B)
__device__ float g_as1[Nn * H1c];
__device__ float g_ad1[Nn * H1c];
__device__ float g_as2[Nn];
__device__ float g_ad2[Nn];
__device__ int   g_deg[Nn];
__device__ int   g_rowstart[Nn + 1];
__device__ int   g_cursor[Nn];
__device__ int   g_flag[SC_BLOCKS];
__device__ int   g_aggv[SC_BLOCKS];
__device__ int   g_inclv[SC_BLOCKS];
__device__ float4 g_csrA[ET];   // {ex0,ex1,ex2,ex3}
__device__ float4 g_csrB[ET];   // {x0,x1,x2,x3}
__device__ float4 g_csrC[ET];   // {x4, e2, src, -}
__device__ float g_eamean[EDD];
__device__ float g_eapart[EAP_BLOCKS * EDD];
__device__ float g_aev1[H1c * EDD];
__device__ float g_aev2[EDD];
__device__ float g_us1[H1c * IND];
__device__ float g_ud1[H1c * IND];
__device__ float g_us2[D1];
__device__ float g_ud2[D1];

// ---------------- small helpers --------------------------------------------
__device__ __forceinline__ uint32_t smem_u32(const void* p) {
    uint32_t a;
    asm("{ .reg .u64 t; cvta.to.shared.u64 t, %1; cvt.u32.u64 %0, t; }" : "=r"(a) : "l"(p));
    return a;
}
__device__ __forceinline__ void cp_async16(uint32_t dst, const void* src) {
    asm volatile("cp.async.cg.shared.global [%0], [%1], 16;" :: "r"(dst), "l"(src));
}
#define CP_COMMIT() asm volatile("cp.async.commit_group;" ::: "memory")
#define CP_WAIT1()  asm volatile("cp.async.wait_group 1;" ::: "memory")
#define CP_WAIT0()  asm volatile("cp.async.wait_group 0;" ::: "memory")

__device__ __forceinline__ float warp_red(float v) {
#pragma unroll
    for (int off = 16; off > 0; off >>= 1)
        v += __shfl_down_sync(0xffffffffu, v, off);
    return v;
}

__device__ __forceinline__ float warp_dot128(const float* a, const float* b, int lane) {
    float s = 0.f;
#pragma unroll
    for (int c = 0; c < 4; c++) s = fmaf(a[lane + 32 * c], b[lane + 32 * c], s);
    return warp_red(s);
}

// block-wide inclusive scan helper (256 threads)
__device__ __forceinline__ int block_scan_incl(int v, int t, int* total_out) {
    int lane = t & 31, w = t >> 5;
    int sv = v;
#pragma unroll
    for (int off = 1; off < 32; off <<= 1) {
        int nv = __shfl_up_sync(0xffffffffu, sv, off);
        if (lane >= off) sv += nv;
    }
    __shared__ int ws[8];
    __shared__ int wo[8];
    __shared__ int tot;
    if (lane == 31) ws[w] = sv;
    __syncthreads();
    if (t == 0) {
        int run = 0;
#pragma unroll
        for (int k = 0; k < 8; k++) { wo[k] = run; run += ws[k]; }
        tot = run;
    }
    __syncthreads();
    *total_out = tot;
    return sv + wo[w];
}

// ---------------- kernels --------------------------------------------------

// fused: ea partial sums | W2->bf16 | degree count | u/aev precompute
__global__ void k_init(const float* __restrict__ ea,  const float* __restrict__ W2,
                       const int*   __restrict__ ei,
                       const float* __restrict__ W1,  const float* __restrict__ We1,
                       const float* __restrict__ We2,
                       const float* __restrict__ as1, const float* __restrict__ ad1,
                       const float* __restrict__ ae1,
                       const float* __restrict__ as2, const float* __restrict__ ad2,
                       const float* __restrict__ ae2) {
    int b = blockIdx.x, t = threadIdx.x;
    if (b < IB_EAP) {
        __shared__ float sm[256 * EDD];
        float loc[EDD];
#pragma unroll
        for (int d = 0; d < EDD; d++) loc[d] = 0.f;
        int r0 = b * EAP_ROWS;
        for (int r = t; r < EAP_ROWS; r += 256) {
            const float* p = ea + (size_t)(r0 + r) * EDD;
#pragma unroll
            for (int d = 0; d < EDD; d++) loc[d] += p[d];
        }
#pragma unroll
        for (int d = 0; d < EDD; d++) sm[t * EDD + d] = loc[d];
        __syncthreads();
        for (int off = 128; off > 0; off >>= 1) {
            if (t < off) {
#pragma unroll
                for (int d = 0; d < EDD; d++) sm[t * EDD + d] += sm[(t + off) * EDD + d];
            }
            __syncthreads();
        }
        if (t < EDD) g_eapart[b * EDD + t] = sm[t];
    } else if (b < IB_EAP + IB_W2) {
        int idx = ((b - IB_EAP) * 256 + t) * 4;
        float4 v = *(const float4*)&W2[idx];
        __nv_bfloat162 lo = __float22bfloat162_rn(make_float2(v.x, v.y));
        __nv_bfloat162 hi = __float22bfloat162_rn(make_float2(v.z, v.w));
        *(uint2*)&g_W2b[idx] = make_uint2(*(uint32_t*)&lo, *(uint32_t*)&hi);
    } else if (b < IB_EAP + IB_W2 + IB_CNT) {
        int e0 = ((b - IB_EAP - IB_W2) * 256 + t) * 4;
#pragma unroll
        for (int k = 0; k < 4; k++) {
            int e = e0 + k;
            if (e < ET) {
                int d = (e < Ee) ? ei[Ee + e] : (e - Ee);
                atomicAdd(&g_deg[d], 1);
            }
        }
    } else if (b < IB_EAP + IB_W2 + IB_CNT + IB_US2) {
        int g = (b - IB_EAP - IB_W2 - IB_CNT) * 8 + (t >> 5);   // 0..1023
        int lane = t & 31;
        if (g < 512) {
            float s = warp_dot128(W2 + (size_t)g * HIDc, as2, lane);
            if (lane == 0) g_us2[g] = s;
        } else {
            int k = g - 512;
            float s = warp_dot128(W2 + (size_t)k * HIDc, ad2, lane);
            if (lane == 0) g_ud2[k] = s;
        }
    } else {
        int g = (b - IB_EAP - IB_W2 - IB_CNT - IB_US2) * 8 + (t >> 5);  // 0..95
        int lane = t & 31;
        if (g < 44) {                       // aev1[h][d]
            int h = g / EDD, d = g % EDD;
            float s = 0.f;
#pragma unroll
            for (int c = 0; c < 4; c++)
                s = fmaf(We1[d * D1 + h * HIDc + lane + 32 * c],
                         ae1[h * HIDc + lane + 32 * c], s);
            s = warp_red(s);
            if (lane == 0) g_aev1[g] = s;
        } else if (g < 55) {                // aev2[d]
            int d = g - 44;
            float s = warp_dot128(We2 + (size_t)d * HIDc, ae2, lane);
            if (lane == 0) g_aev2[d] = s;
        } else if (g < 75) {                // us1[h*5+d]
            int o = g - 55, h = o / IND, d = o % IND;
            float s = 0.f;
#pragma unroll
            for (int c = 0; c < 4; c++)
                s = fmaf(W1[d * D1 + h * HIDc + lane + 32 * c],
                         as1[h * HIDc + lane + 32 * c], s);
            s = warp_red(s);
            if (lane == 0) g_us1[o] = s;
        } else if (g < 95) {                // ud1[h*5+d]
            int o = g - 75, h = o / IND, d = o % IND;
            float s = 0.f;
#pragma unroll
            for (int c = 0; c < 4; c++)
                s = fmaf(W1[d * D1 + h * HIDc + lane + 32 * c],
                         ad1[h * HIDc + lane + 32 * c], s);
            s = warp_red(s);
            if (lane == 0) g_ud1[o] = s;
        }
    }
}

// fused: decoupled-lookback scan (blocks 0..156) | eamean (157) | node1 (158+)
__global__ void k_mid(const float* __restrict__ x) {
    int b = blockIdx.x, t = threadIdx.x;
    if (b < SC_BLOCKS) {
        int i = b * 256 + t;
        int v = (i < Nn) ? g_deg[i] : 0;
        int tot;
        int incl = block_scan_incl(v, t, &tot);
        __shared__ int s_off;
        volatile int* flag = g_flag;
        volatile int* aggv = g_aggv;
        volatile int* inclv = g_inclv;
        if (t == 0) {
            if (b == 0) {
                inclv[0] = tot; __threadfence(); flag[0] = 2;
                s_off = 0;
            } else {
                aggv[b] = tot; __threadfence(); flag[b] = 1;
                int run = 0, j = b - 1;
                while (true) {
                    int f;
                    do { f = flag[j]; } while (f == 0);
                    if (f == 2) { run += inclv[j]; break; }
                    run += aggv[j]; j--;
                }
                inclv[b] = run + tot; __threadfence(); flag[b] = 2;
                s_off = run;
            }
        }
        __syncthreads();
        int r = s_off + incl - v;
        if (i < Nn) { g_rowstart[i] = r; g_cursor[i] = r; }
        if (b == SC_BLOCKS - 1 && t == 255) g_rowstart[Nn] = ET;
    } else if (b == SC_BLOCKS) {
        int w = t >> 5, lane = t & 31;
        for (int col = w; col < EDD; col += 8) {
            float s = 0.f;
            for (int p = lane; p < EAP_BLOCKS; p += 32) s += g_eapart[p * EDD + col];
            s = warp_red(s);
            if (lane == 0) g_eamean[col] = s / (float)Ee;
        }
    } else {
        int idx = (b - SC_BLOCKS - 1) * 256 + t;
        int n = idx >> 3;
        if (n >= Nn) return;
        int r = idx & 7;
        int h = r & 3;
        const float* xp = x + (size_t)n * IND;
        g_x8[(size_t)n * 8 + r] = (r < IND) ? xp[r] : 0.f;
        const float* u = (r < 4) ? (g_us1 + h * IND) : (g_ud1 + h * IND);
        float s = 0.f;
#pragma unroll
        for (int d = 0; d < IND; d++) s += xp[d] * u[d];
        if (r < 4) g_as1[n * H1c + h] = s;
        else       g_ad1[n * H1c + h] = s;
    }
}

// CSR scatter, SoA: A={ex0..3} B={x0..3} C={x4,e2,src}.
__global__ void k_scatter(const int* __restrict__ ei, const float* __restrict__ ea) {
    int e = blockIdx.x * blockDim.x + threadIdx.x;
    if (e >= ET) return;
    int s, d;
    float v[EDD];
    if (e < Ee) {
        s = ei[e]; d = ei[Ee + e];
        const float* p = ea + (size_t)e * EDD;
#pragma unroll
        for (int k = 0; k < EDD; k++) v[k] = p[k];
    } else {
        s = e - Ee; d = s;
#pragma unroll
        for (int k = 0; k < EDD; k++) v[k] = g_eamean[k];
    }
    int pos = atomicAdd(&g_cursor[d], 1);
    float e2 = 0.f;
#pragma unroll
    for (int k = 0; k < EDD; k++) e2 += v[k] * g_aev2[k];

    float4 asv = *(const float4*)&g_as1[s * H1c];
    float4 adv = *(const float4*)&g_ad1[d * H1c];
    float al[H1c];
#pragma unroll
    for (int h = 0; h < H1c; h++) {
        float ed = 0.f;
#pragma unroll
        for (int k = 0; k < EDD; k++) ed += v[k] * g_aev1[h * EDD + k];
        float a = ((h == 0) ? asv.x : (h == 1) ? asv.y : (h == 2) ? asv.z : asv.w)
                + ((h == 0) ? adv.x : (h == 1) ? adv.y : (h == 2) ? adv.z : adv.w) + ed;
        a = (a > 0.f) ? a : NEG * a;
        al[h] = __expf(a);
    }
    const float* xp = g_x8 + (size_t)s * 8;
    float4 xv4 = __ldg((const float4*)xp);
    float xv5 = __ldg(xp + 4);
    g_csrA[pos] = make_float4(al[0], al[1], al[2], al[3]);
    g_csrB[pos] = xv4;
    g_csrC[pos] = make_float4(xv5, e2, __int_as_float(s), 0.f);
}

// layer-1 softmax + aggregation + projection.
// Phase 1: 8 lanes per node (4 nodes/warp, 32 nodes/block), 3-step butterfly.
// Phase 2: thread-per-channel-pair projection, W1/b1 in regs (32 nodes amortized).
// Phase 3: 8-lane-per-node as2/ad2 reduction from padded smem h1.
__global__ __launch_bounds__(256) void k_agg1(const float* __restrict__ W1,
                                              const float* __restrict__ b1) {
    __shared__ float s_ax[32][21];
    __shared__ uint32_t s_h1[32][264];      // pad 264: grp*8+j hits distinct banks
    __shared__ float s_u[D1];
    __shared__ float s_ud[D1];
    int t = threadIdx.x;
    int w = t >> 5, lane = t & 31;
    int grp = lane >> 3, j = lane & 7;
    int n0 = blockIdx.x * 32;
    int nl = w * 4 + grp;                   // local node 0..31
    int n = n0 + nl;                        // Nn % 32 == 0

#pragma unroll
    for (int i = 0; i < 2; i++) {
        s_u [t + i * 256] = g_us2[t + i * 256];
        s_ud[t + i * 256] = g_ud2[t + i * 256];
    }

    // ---- phase 1: 8-lane gather ----
    int base = g_rowstart[n];
    int deg  = g_rowstart[n + 1] - base;

    float den[H1c];
    float ax[H1c][IND];
#pragma unroll
    for (int h = 0; h < H1c; h++) {
        den[h] = 0.f;
#pragma unroll
        for (int d = 0; d < IND; d++) ax[h][d] = 0.f;
    }

    for (int i = j; i < deg; i += 8) {
        float4 exv = g_csrA[base + i];
        float4 xa  = g_csrB[base + i];
        float4 xc  = g_csrC[base + i];
        float e0 = exv.x, e1 = exv.y, e2 = exv.z, e3 = exv.w;
        den[0] += e0; den[1] += e1; den[2] += e2; den[3] += e3;
        float xv[IND] = {xa.x, xa.y, xa.z, xa.w, xc.x};
#pragma unroll
        for (int d = 0; d < IND; d++) {
            ax[0][d] = fmaf(e0, xv[d], ax[0][d]);
            ax[1][d] = fmaf(e1, xv[d], ax[1][d]);
            ax[2][d] = fmaf(e2, xv[d], ax[2][d]);
            ax[3][d] = fmaf(e3, xv[d], ax[3][d]);
        }
    }
    // 3-step butterfly within the 8-lane group
#pragma unroll
    for (int off = 4; off > 0; off >>= 1) {
#pragma unroll
        for (int h = 0; h < H1c; h++) {
            den[h] += __shfl_xor_sync(0xffffffffu, den[h], off);
#pragma unroll
            for (int d = 0; d < IND; d++)
                ax[h][d] += __shfl_xor_sync(0xffffffffu, ax[h][d], off);
        }
    }
    if (j < H1c) {   // lane j handles head j (ternary selects, no dyn indexing)
        float dh = (j == 0) ? den[0] : (j == 1) ? den[1] : (j == 2) ? den[2] : den[3];
        float inv = 1.f / (dh + 1e-16f);
        float v0 = (j == 0) ? ax[0][0] : (j == 1) ? ax[1][0] : (j == 2) ? ax[2][0] : ax[3][0];
        float v1 = (j == 0) ? ax[0][1] : (j == 1) ? ax[1][1] : (j == 2) ? ax[2][1] : ax[3][1];
        float v2 = (j == 0) ? ax[0][2] : (j == 1) ? ax[1][2] : (j == 2) ? ax[2][2] : ax[3][2];
        float v3 = (j == 0) ? ax[0][3] : (j == 1) ? ax[1][3] : (j == 2) ? ax[2][3] : ax[3][3];
        float v4 = (j == 0) ? ax[0][4] : (j == 1) ? ax[1][4] : (j == 2) ? ax[2][4] : ax[3][4];
        s_ax[nl][j * IND + 0] = v0 * inv;
        s_ax[nl][j * IND + 1] = v1 * inv;
        s_ax[nl][j * IND + 2] = v2 * inv;
        s_ax[nl][j * IND + 3] = v3 * inv;
        s_ax[nl][j * IND + 4] = v4 * inv;
    }
    __syncthreads();

    // ---- phase 2: projection, W1/b1 in regs once per block (32 nodes) ----
    int c0 = t * 2;
    int h2 = c0 >> 7;
    float2 wv[IND];
#pragma unroll
    for (int d = 0; d < IND; d++) wv[d] = *(const float2*)&W1[d * D1 + c0];
    float2 bb = *(const float2*)&b1[c0];

#pragma unroll
    for (int q = 0; q < 32; q++) {
        float a0 = bb.x, a1 = bb.y;
#pragma unroll
        for (int d = 0; d < IND; d++) {
            float av = s_ax[q][h2 * IND + d];
            a0 = fmaf(av, wv[d].x, a0);
            a1 = fmaf(av, wv[d].y, a1);
        }
        a0 = (a0 > 0.f) ? a0 : 0.f;
        a1 = (a1 > 0.f) ? a1 : 0.f;
        __nv_bfloat162 bv = __float22bfloat162_rn(make_float2(a0, a1));
        *(__nv_bfloat162*)(g_h1b + (size_t)(n0 + q) * D1 + c0) = bv;
        s_h1[q][t] = *(uint32_t*)&bv;
    }
    __syncthreads();

    // ---- phase 3: 8-lane-per-node as2/ad2 reduction ----
    float s2 = 0.f, d2v = 0.f;
#pragma unroll
    for (int k = 0; k < 32; k++) {
        int c = j + 8 * k;
        uint32_t raw = s_h1[nl][c];
        float2 f = __bfloat1622float2(*(__nv_bfloat162*)&raw);
        s2  = fmaf(f.x, s_u [2 * c], fmaf(f.y, s_u [2 * c + 1], s2));
        d2v = fmaf(f.x, s_ud[2 * c], fmaf(f.y, s_ud[2 * c + 1], d2v));
    }
#pragma unroll
    for (int off = 4; off > 0; off >>= 1) {
        s2  += __shfl_xor_sync(0xffffffffu, s2, off);
        d2v += __shfl_xor_sync(0xffffffffu, d2v, off);
    }
    if (j == 0) { g_as2[n] = s2; g_ad2[n] = d2v; }
}

// xh2 = h1 @ W2 : bf16 wmma (HMMA), 128x128 CTA tile, K chunks of 64,
// cp.async double-buffered; bf16x2 packed output staged through smem.
#define KC 64
#define A_ELEMS 9216    /* 128 * 72 */
#define B_ELEMS 8704    /* 64 * 136 */
#define A_BYTES 18432
#define B_BYTES 17408
#define GSM_TOTAL (2 * (A_BYTES + B_BYTES))   /* 71680 >= 65536 for C staging */

__global__ __launch_bounds__(256, 2) void k_gemm() {
    extern __shared__ char smc[];
    __nv_bfloat16* As = (__nv_bfloat16*)smc;                     // [2][128][72]
    __nv_bfloat16* Bs = (__nv_bfloat16*)(smc + 2 * A_BYTES);     // [2][64][136]
    uint32_t smA = smem_u32(As);
    uint32_t smB = smem_u32(Bs);

    int t = threadIdx.x;
    int wid = t >> 5;
    int row0 = blockIdx.x * 128;
    int wm0 = (wid >> 2) * 64;     // 0 or 64
    int wn0 = (wid & 3) * 32;      // 0,32,64,96

    wmma::fragment<wmma::accumulator, 16, 16, 16, float> acc[4][2];
#pragma unroll
    for (int m = 0; m < 4; m++)
#pragma unroll
        for (int n = 0; n < 2; n++) wmma::fill_fragment(acc[m][n], 0.f);

    auto load_chunk = [&](int buf, int k0) {
#pragma unroll
        for (int i = 0; i < 4; i++) {
            int v = i * 256 + t;
            int r = v >> 3, c8 = v & 7;                 // A: 128 rows x 8 uint4
            cp_async16(smA + (uint32_t)(buf * A_ELEMS + r * 72 + c8 * 8) * 2,
                       g_h1b + (size_t)(row0 + r) * D1 + k0 + c8 * 8);
        }
#pragma unroll
        for (int i = 0; i < 4; i++) {
            int v = i * 256 + t;
            int r = v >> 4, c8 = v & 15;                // B: 64 rows x 16 uint4
            cp_async16(smB + (uint32_t)(buf * B_ELEMS + r * 136 + c8 * 8) * 2,
                       g_W2b + (size_t)(k0 + r) * HIDc + c8 * 8);
        }
        CP_COMMIT();
    };

    load_chunk(0, 0);
    int buf = 0;
#pragma unroll
    for (int c = 0; c < 8; c++) {
        if (c < 7) load_chunk(buf ^ 1, (c + 1) * KC);
        if (c < 7) CP_WAIT1(); else CP_WAIT0();
        __syncthreads();

        const __nv_bfloat16* Ab = As + buf * A_ELEMS;
        const __nv_bfloat16* Bb = Bs + buf * B_ELEMS;
#pragma unroll
        for (int kk = 0; kk < 4; kk++) {
            wmma::fragment<wmma::matrix_a, 16, 16, 16, __nv_bfloat16, wmma::row_major> af[4];
            wmma::fragment<wmma::matrix_b, 16, 16, 16, __nv_bfloat16, wmma::row_major> bf[2];
#pragma unroll
            for (int m = 0; m < 4; m++)
                wmma::load_matrix_sync(af[m], Ab + (wm0 + m * 16) * 72 + kk * 16, 72);
#pragma unroll
            for (int n = 0; n < 2; n++)
                wmma::load_matrix_sync(bf[n], Bb + (kk * 16) * 136 + wn0 + n * 16, 136);
#pragma unroll
            for (int m = 0; m < 4; m++)
#pragma unroll
                for (int n = 0; n < 2; n++)
                    wmma::mma_sync(acc[m][n], af[m], bf[n], acc[m][n]);
        }
        __syncthreads();
        buf ^= 1;
    }

    // stage fp32 C in smem, emit packed bf16x2
    float* Cs = (float*)smc;    // 128*128 fp32 = 64KB
#pragma unroll
    for (int m = 0; m < 4; m++)
#pragma unroll
        for (int n = 0; n < 2; n++)
            wmma::store_matrix_sync(Cs + (size_t)(wm0 + m * 16) * 128 + wn0 + n * 16,
                                    acc[m][n], 128, wmma::mem_row_major);
    __syncthreads();
#pragma unroll
    for (int j = 0; j < 32; j++) {
        int idx = j * 256 + t;          // 8192 bf16x2 pairs
        int row = idx >> 6, cp = idx & 63;
        float2 f = *(const float2*)&Cs[row * 128 + cp * 2];
        __nv_bfloat162 bv = __float22bfloat162_rn(f);
        g_xh2b[(size_t)(row0 + row) * 64 + cp] = *(uint32_t*)&bv;
    }
}

// layer-2 softmax + aggregation + final linear + sigmoid, warp-per-node.
__global__ __launch_bounds__(256) void k_agg2(const float* __restrict__ b2,
                                              const float* __restrict__ Wfc,
                                              const float* __restrict__ bfc,
                                              float* __restrict__ out) {
    int t = threadIdx.x;
    int w = t >> 5, lane = t & 31;
    int n = blockIdx.x * 8 + w;            // Nn % 8 == 0
    int base = g_rowstart[n];
    int deg  = g_rowstart[n + 1] - base;
    float ad = g_ad2[n];

    float acc0 = 0.f, acc1 = 0.f, acc2 = 0.f, acc3 = 0.f;
    float den = 0.f;

    for (int b0 = 0; b0 < deg; b0 += 32) {
        float ex = 0.f; int src = 0;
        int i = b0 + lane;
        if (i < deg) {
            float4 f = g_csrC[base + i];
            src = __float_as_int(f.z);
            float al = g_as2[src] + ad + f.y;
            al = (al > 0.f) ? al : NEG * al;
            ex = __expf(al);
        }
        den += ex;
        int cnt = deg - b0; if (cnt > 32) cnt = 32;
        for (int j = 0; j < cnt; j++) {
            float exj = __shfl_sync(0xffffffffu, ex, j);
            int srcj  = __shfl_sync(0xffffffffu, src, j);
            uint2 raw = *(const uint2*)&g_xh2b[(size_t)srcj * 64 + lane * 2];
            float2 f0 = __bfloat1622float2(*(__nv_bfloat162*)&raw.x);
            float2 f1 = __bfloat1622float2(*(__nv_bfloat162*)&raw.y);
            acc0 = fmaf(exj, f0.x, acc0);
            acc1 = fmaf(exj, f0.y, acc1);
            acc2 = fmaf(exj, f1.x, acc2);
            acc3 = fmaf(exj, f1.y, acc3);
        }
    }
#pragma unroll
    for (int off = 16; off > 0; off >>= 1)
        den += __shfl_xor_sync(0xffffffffu, den, off);
    float inv = 1.f / (den + 1e-16f);

    float4 bb = *(const float4*)&b2[lane * 4];
    float4 wf = *(const float4*)&Wfc[lane * 4];
    float h0 = acc0 * inv + bb.x; h0 = (h0 > 0.f) ? h0 : 0.f;
    float h1 = acc1 * inv + bb.y; h1 = (h1 > 0.f) ? h1 : 0.f;
    float h2 = acc2 * inv + bb.z; h2 = (h2 > 0.f) ? h2 : 0.f;
    float h3 = acc3 * inv + bb.w; h3 = (h3 > 0.f) ? h3 : 0.f;
    float part = fmaf(h0, wf.x, fmaf(h1, wf.y, fmaf(h2, wf.z, h3 * wf.w)));
    part = warp_red(part);
    if (lane == 0) {
        float z = part + bfc[0];
        out[n] = 1.f / (1.f + __expf(-z));
    }
}

// ---------------- launcher -------------------------------------------------

extern "C" void kernel_launch(void* const* d_in, const int* in_sizes, int n_in,
                              void* d_out, int out_size) {
    const float* x    = (const float*)d_in[0];
    const int*   ei   = (const int*)  d_in[1];
    const float* ea   = (const float*)d_in[2];
    const float* W1   = (const float*)d_in[3];
    const float* We1  = (const float*)d_in[4];
    const float* as1v = (const float*)d_in[5];
    const float* ad1v = (const float*)d_in[6];
    const float* ae1v = (const float*)d_in[7];
    const float* b1   = (const float*)d_in[8];
    const float* W2   = (const float*)d_in[9];
    const float* We2  = (const float*)d_in[10];
    const float* as2v = (const float*)d_in[11];
    const float* ad2v = (const float*)d_in[12];
    const float* ae2v = (const float*)d_in[13];
    const float* b2   = (const float*)d_in[14];
    const float* Wfc  = (const float*)d_in[15];
    const float* bfc  = (const float*)d_in[16];
    float* out = (float*)d_out;

    static void* p_deg = nullptr;
    static void* p_flag = nullptr;
    if (!p_deg) {
        cudaFuncSetAttribute(k_gemm, cudaFuncAttributeMaxDynamicSharedMemorySize, GSM_TOTAL);
        cudaGetSymbolAddress(&p_deg, g_deg);
        cudaGetSymbolAddress(&p_flag, g_flag);
    }

    cudaMemsetAsync(p_deg, 0, Nn * sizeof(int));
    cudaMemsetAsync(p_flag, 0, SC_BLOCKS * sizeof(int));
    k_init<<<IB_TOTAL, 256>>>(ea, W2, ei, W1, We1, We2,
                              as1v, ad1v, ae1v, as2v, ad2v, ae2v);
    k_mid<<<SC_BLOCKS + 1 + N1_BLOCKS, 256>>>(x);
    k_scatter<<<(ET + 255) / 256, 256>>>(ei, ea);
    k_agg1<<<Nn / 32, 256>>>(W1, b1);
    k_gemm<<<MROWS / 128, 256, GSM_TOTAL>>>();
    k_agg2<<<Nn / 8, 256>>>(b2, Wfc, bfc, out);
}